// round 6
// baseline (speedup 1.0000x reference)
#include <cuda_runtime.h>
#include <cstdint>

#define C 128
#define HH 320
#define WW 320
#define BB 2
#define SEG 80
#define NBLK (BB*HH*(WW/SEG))   // 2560
#define NTH 320
#define KCH 8                   // k-chunk size
#define NCH (C/KCH)             // 16 chunks

typedef unsigned long long u64;

// ---------------- device scratch ----------------
// g_WC[t][k][r] f32: combined weight. r<128: epi row; r in [128,160): dm1-folded row. t=0:H,1:V.
__device__ float g_WC[2*C*160];
__device__ float g_dm2t[32*C];    // [j][c] = dm2[c][j]

// ---------------- f32x2 helpers ----------------
__device__ __forceinline__ u64 splat2(float w) {
    u64 r; unsigned u = __float_as_uint(w);
    asm("mov.b64 %0, {%1, %1};" : "=l"(r) : "r"(u));
    return r;
}
__device__ __forceinline__ u64 pack2(float a, float b) {
    u64 r;
    asm("mov.b64 %0, {%1, %2};" : "=l"(r) : "r"(__float_as_uint(a)), "r"(__float_as_uint(b)));
    return r;
}
__device__ __forceinline__ void unpack2(u64 v, float& a, float& b) {
    unsigned x, y; asm("mov.b64 {%0, %1}, %2;" : "=r"(x), "=r"(y) : "l"(v));
    a = __uint_as_float(x); b = __uint_as_float(y);
}
__device__ __forceinline__ u64 ffma2(u64 a, u64 b, u64 c) {
    u64 d;
    asm("fma.rn.f32x2 %0, %1, %2, %3;" : "=l"(d) : "l"(a), "l"(b), "l"(c));
    return d;
}
__device__ __forceinline__ float lrelu(float v) { return v > 0.f ? v : 0.1f * v; }
__device__ __forceinline__ void cp_async16(uint32_t saddr, const void* g) {
    asm volatile("cp.async.ca.shared.global [%0], [%1], 16;" :: "r"(saddr), "l"(g));
}

// ---------------- fold kernel ----------------
#define SMEM_FOLD ((128*129*2 + 32*129 + 4*128) * 4)
__global__ void __launch_bounds__(256) k_fold(
    const float* __restrict__ wf,   // [128][256]
    const float* __restrict__ pwh,  // [128][128]
    const float* __restrict__ pwv,  // [128][128]
    const float* __restrict__ dm1,  // [32][128]
    const float* __restrict__ dm2)  // [128][32]
{
    extern __shared__ float s[];
    float* FU = s;              // fuse_H [128][129]
    float* FV = s + 16512;      // fuse_V [128][129]
    float* D1 = s + 33024;      // dm1 [32][129]
    float* cH = s + 37152;      // [128] pw col, later reused for dH
    float* cV = cH + 128;
    float* wH = cV + 128;       // [128]
    float* wV = wH + 128;
    const int k = blockIdx.x;
    const int tid = threadIdx.x;

    for (int i = tid; i < 128*128; i += 256) {
        int m = i >> 7, c = i & 127;
        FU[m*129 + c] = wf[m*256 + c];
        FV[m*129 + c] = wf[m*256 + 128 + c];
    }
    for (int i = tid; i < 32*128; i += 256)
        D1[(i >> 7)*129 + (i & 127)] = dm1[i];
    if (tid < 128) { cH[tid] = pwh[tid*128 + k]; cV[tid] = pwv[tid*128 + k]; }
    __syncthreads();

    {   // wH[m] = dot(fuse_H[m][:], pwh[:,k]); wV likewise
        int m = tid & 127;
        bool v = tid >= 128;
        const float* row = (v ? FV : FU) + m*129;
        const float* col = v ? cV : cH;
        float a = 0.f;
        #pragma unroll 8
        for (int c = 0; c < 128; ++c) a = fmaf(row[c], col[c], a);
        (v ? wV : wH)[m] = a;
    }
    __syncthreads();

    if (tid < 64) {  // dH[j] = dot(dm1[j][:], wH[:])
        int j = tid & 31;
        int t = tid >> 5;
        const float* w = t ? wV : wH;
        float a = 0.f;
        #pragma unroll 8
        for (int m = 0; m < 128; ++m) a = fmaf(D1[j*129 + m], w[m], a);
        (t ? cV : cH)[j] = a;
    }
    __syncthreads();

    for (int i = tid; i < 2*160; i += 256) {
        int t = i / 160, r = i - t*160;
        float val = (r < 128) ? (t ? wV : wH)[r] : (t ? cV : cH)[r - 128];
        g_WC[((size_t)t*C + k)*160 + r] = val;
    }
    if (k == 0) {
        for (int i = tid; i < 128*32; i += 256) {
            int c = i >> 5, j = i & 31;
            g_dm2t[j*128 + c] = dm2[c*32 + j];
        }
    }
}

// ---------------- main fused kernel ----------------
// grid 2560 = 640 rows x 4 segments of 80; 320 threads; 2 CTAs/SM.
// smem (floats): Th[0,10240) Tv[10240,20480) wbuf[20480,25600)  (2 bufs x 2 tensors x 8k x 160)
//                dwhs[25600,26240) dwvs[26240,26880)
// overlays after GEMM: Esm [128][84] at 0, Usm [32][88] at 10752.
#define SMEM_MAIN (26880 * 4)

__global__ void __launch_bounds__(NTH, 2) k_main(
    const float* __restrict__ x,
    const float* __restrict__ dwh,      // [128][5]
    const float* __restrict__ dwv,      // [128][5]
    const float* __restrict__ scale_p,
    float* __restrict__ out)
{
    extern __shared__ float sm[];
    float* Th   = sm;
    float* Tv   = sm + 10240;
    float* wbuf = sm + 20480;     // [2][2][KCH][160]
    float* dwhs = sm + 25600;
    float* dwvs = sm + 26240;
    float* Esm  = sm;             // [c][p] stride 84
    float* Usm  = sm + 10752;     // [j][p] stride 88

    const int tid = threadIdx.x;
    const int bx  = blockIdx.x;
    const int seg = bx & 3;
    const int row = bx >> 2;
    const int b   = row / HH;
    const int y   = row - b * HH;
    const int ai  = y % 5;
    const int y0  = y - ai;
    const int x0  = seg * SEG;

    const uint32_t wbuf_s = (uint32_t)__cvta_generic_to_shared(wbuf);

    // ---- kick off weight prefetch for chunk 0 (overlaps with stage 1) ----
    {
        uint32_t dst = wbuf_s + tid*16;
        cp_async16(dst,                 (const char*)g_WC + tid*16);
        cp_async16(dst + KCH*160*4,     (const char*)g_WC + (size_t)C*160*4 + tid*16);
        asm volatile("cp.async.commit_group;");
    }

    for (int i = tid; i < 640; i += NTH) { dwhs[i] = dwh[i]; dwvs[i] = dwv[i]; }
    __syncthreads();

    // ---- stage 1: depthwise convs + lrelu -> Th/Tv [128][80] ----
    const float* xb = x + (size_t)b * C * HH * WW;
    #pragma unroll 2
    for (int it = 0; it < 32; ++it) {
        int i = tid + NTH * it;
        int k = i / SEG;
        int p = i - k * SEG;
        int aj = p % 5;
        const float* xp = xb + ((size_t)k * HH + y0) * WW + x0 + p;
        const float* xr = xb + ((size_t)k * HH + y)  * WW + x0 + p;
        float v0 = xp[0], v1 = xp[WW], v2 = xp[2*WW], v3 = xp[3*WW], v4 = xp[4*WW];
        float tv = 0.f;
        #pragma unroll
        for (int r = 0; r < 5; ++r) {
            int q = r - ai + 2;
            float vr = (r == 0) ? v0 : (r == 1) ? v1 : (r == 2) ? v2 : (r == 3) ? v3 : v4;
            if ((unsigned)q < 5u) tv = fmaf(dwvs[k*5 + q], vr, tv);
        }
        float vai = (ai == 0) ? v0 : (ai == 1) ? v1 : (ai == 2) ? v2 : (ai == 3) ? v3 : v4;
        float th = dwhs[k*5 + 2] * vai;
        if (aj >= 2) th = fmaf(dwhs[k*5 + 0], xr[-2], th);
        if (aj >= 1) th = fmaf(dwhs[k*5 + 1], xr[-1], th);
        if (aj <= 3) th = fmaf(dwhs[k*5 + 3], xr[ 1], th);
        if (aj <= 2) th = fmaf(dwhs[k*5 + 4], xr[ 2], th);
        Th[k*SEG + p] = lrelu(th);
        Tv[k*SEG + p] = lrelu(tv);
    }

    // ---- GEMM: [epi;u_pre][160][80] = W_H @ Th + W_V @ Tv, k-chunked smem weights ----
    const int lane = tid & 31;
    const int wrp  = tid >> 5;
    const int band = wrp % 5;
    const int half = wrp / 5;
    const int rl   = lane & 7;
    const int pl   = lane >> 3;
    const int r0   = band*32 + rl*4;
    const int p0   = half*40 + pl*10;

    u64 acc[4][5];
    #pragma unroll
    for (int i = 0; i < 4; ++i)
        #pragma unroll
        for (int s = 0; s < 5; ++s) acc[i][s] = 0ull;

    const float* thp = Th + p0;
    const float* tvp = Tv + p0;

    for (int c = 0; c < NCH; ++c) {
        __syncthreads();   // prev compute done (and stage1 done when c==0) before overwriting next buf
        if (c + 1 < NCH) {
            uint32_t dst = wbuf_s + ((c + 1) & 1) * (2*KCH*160*4) + tid*16;
            const char* srcH = (const char*)g_WC + (size_t)(c + 1)*KCH*160*4 + tid*16;
            cp_async16(dst,             srcH);
            cp_async16(dst + KCH*160*4, srcH + (size_t)C*160*4);
        }
        asm volatile("cp.async.commit_group;");
        asm volatile("cp.async.wait_group 1;");
        __syncthreads();   // buf[c&1] visible to all

        const float* wbH = wbuf + (c & 1) * (2*KCH*160) + r0;
        const float* wbV = wbH + KCH*160;
        const float* tc  = thp + c*KCH*SEG;
        const float* vc  = tvp + c*KCH*SEG;
        #pragma unroll 2
        for (int kk = 0; kk < KCH; ++kk) {
            float4 h4 = *(const float4*)(wbH + kk*160);
            float4 v4 = *(const float4*)(wbV + kk*160);
            u64 hw[4] = { splat2(h4.x), splat2(h4.y), splat2(h4.z), splat2(h4.w) };
            u64 vw[4] = { splat2(v4.x), splat2(v4.y), splat2(v4.z), splat2(v4.w) };
            u64 th2[5], tv2[5];
            #pragma unroll
            for (int s = 0; s < 5; ++s) {
                th2[s] = *(const u64*)(tc + kk*SEG + 2*s);
                tv2[s] = *(const u64*)(vc + kk*SEG + 2*s);
            }
            #pragma unroll
            for (int i = 0; i < 4; ++i)
                #pragma unroll
                for (int s = 0; s < 5; ++s) {
                    acc[i][s] = ffma2(hw[i], th2[s], acc[i][s]);
                    acc[i][s] = ffma2(vw[i], tv2[s], acc[i][s]);
                }
        }
    }
    __syncthreads();   // done reading Th/Tv

    // ---- scatter: epi rows -> Esm [c][p], u rows (r>=128) -> lrelu -> Usm ----
    #pragma unroll
    for (int i = 0; i < 4; ++i) {
        int r = r0 + i;
        if (r < 128) {
            #pragma unroll
            for (int s = 0; s < 5; ++s)
                *(u64*)(Esm + r*84 + p0 + 2*s) = acc[i][s];
        } else {
            int j = r - 128;
            #pragma unroll
            for (int s = 0; s < 5; ++s) {
                float a, b2; unpack2(acc[i][s], a, b2);
                *(u64*)(Usm + j*88 + p0 + 2*s) = pack2(lrelu(a), lrelu(b2));
            }
        }
    }
    __syncthreads();

    // ---- dm2 @ u -> sigmoid gate; out = x + scl * epi * gate ----
    const int pq = tid % 10;
    const int cg = tid / 10;
    const int c0 = cg * 4;
    const int q0 = pq * 8;
    u64 a2[4][4];
    #pragma unroll
    for (int i = 0; i < 4; ++i)
        #pragma unroll
        for (int s = 0; s < 4; ++s) a2[i][s] = 0ull;

    #pragma unroll 4
    for (int j = 0; j < 32; ++j) {
        float4 w = __ldg((const float4*)(g_dm2t + j*128 + c0));
        u64 w2[4] = { splat2(w.x), splat2(w.y), splat2(w.z), splat2(w.w) };
        ulonglong2 ua = *(const ulonglong2*)(Usm + j*88 + q0);
        ulonglong2 ub = *(const ulonglong2*)(Usm + j*88 + q0 + 4);
        u64 up[4] = { ua.x, ua.y, ub.x, ub.y };
        #pragma unroll
        for (int i = 0; i < 4; ++i)
            #pragma unroll
            for (int s = 0; s < 4; ++s) a2[i][s] = ffma2(w2[i], up[s], a2[i][s]);
    }

    const float scl = scale_p[0];
    #pragma unroll
    for (int i = 0; i < 4; ++i) {
        int c = c0 + i;
        size_t base = ((size_t)(b*C + c) * HH + y) * WW + x0 + q0;
        #pragma unroll
        for (int s = 0; s < 4; ++s) {
            float s0, s1;
            unpack2(a2[i][s], s0, s1);
            float d0 = __frcp_rn(1.f + __expf(-s0));
            float d1 = __frcp_rn(1.f + __expf(-s1));
            float e0, e1;
            unpack2(*(const u64*)(Esm + c*84 + q0 + 2*s), e0, e1);
            float2 xv = *(const float2*)(x + base + 2*s);
            float2 o;
            o.x = fmaf(scl * d0, e0, xv.x);
            o.y = fmaf(scl * d1, e1, xv.y);
            *(float2*)(out + base + 2*s) = o;
        }
    }
}

// ---------------- launch ----------------
extern "C" void kernel_launch(void* const* d_in, const int* in_sizes, int n_in,
                              void* d_out, int out_size) {
    (void)in_sizes; (void)n_in; (void)out_size;
    const float* x      = (const float*)d_in[0];
    const float* w_h_dw = (const float*)d_in[1];
    const float* w_h_pw = (const float*)d_in[2];
    const float* w_v_dw = (const float*)d_in[3];
    const float* w_v_pw = (const float*)d_in[4];
    const float* w_dm1  = (const float*)d_in[5];
    const float* w_dm2  = (const float*)d_in[6];
    const float* w_fuse = (const float*)d_in[7];
    const float* scale  = (const float*)d_in[8];
    float* out = (float*)d_out;

    cudaFuncSetAttribute(k_fold, cudaFuncAttributeMaxDynamicSharedMemorySize, SMEM_FOLD);
    cudaFuncSetAttribute(k_main, cudaFuncAttributeMaxDynamicSharedMemorySize, SMEM_MAIN);

    k_fold<<<128, 256, SMEM_FOLD>>>(w_fuse, w_h_pw, w_v_pw, w_dm1, w_dm2);
    k_main<<<NBLK, NTH, SMEM_MAIN>>>(x, w_h_dw, w_v_dw, scale, out);
}

// round 12
// speedup vs baseline: 2.1560x; 2.1560x over previous
#include <cuda_runtime.h>
#include <cstdint>

#define C 128
#define HH 320
#define WW 320
#define BB 2
#define SEG 80
#define NBLK (BB*HH*(WW/SEG))   // 2560
#define NTH 320

typedef unsigned long long u64;

// ---------------- device scratch ----------------
// g_WA[kc][168] tf32-rounded floats: A matrix rows m=0..159 (128 epi + 32 dm1-folded),
// combined k: kc<128 -> H tensor col, kc>=128 -> V tensor col.
__device__ __align__(16) float g_WA[256*168];
__device__ __align__(16) float g_dm2t[32*C];    // [j][c] = dm2[c][j]

// ---------------- helpers ----------------
__device__ __forceinline__ u64 splat2(float w) {
    u64 r; unsigned u = __float_as_uint(w);
    asm("mov.b64 %0, {%1, %1};" : "=l"(r) : "r"(u));
    return r;
}
__device__ __forceinline__ u64 pack2(float a, float b) {
    u64 r;
    asm("mov.b64 %0, {%1, %2};" : "=l"(r) : "r"(__float_as_uint(a)), "r"(__float_as_uint(b)));
    return r;
}
__device__ __forceinline__ void unpack2(u64 v, float& a, float& b) {
    unsigned x, y; asm("mov.b64 {%0, %1}, %2;" : "=r"(x), "=r"(y) : "l"(v));
    a = __uint_as_float(x); b = __uint_as_float(y);
}
__device__ __forceinline__ u64 ffma2(u64 a, u64 b, u64 c) {
    u64 d;
    asm("fma.rn.f32x2 %0, %1, %2, %3;" : "=l"(d) : "l"(a), "l"(b), "l"(c));
    return d;
}
__device__ __forceinline__ float lrelu(float v) { return v > 0.f ? v : 0.1f * v; }
__device__ __forceinline__ float tf32r(float v) {
    uint32_t t; asm("cvt.rna.tf32.f32 %0, %1;" : "=r"(t) : "f"(v));
    return __uint_as_float(t);
}
__device__ __forceinline__ void cp_async16(uint32_t saddr, const void* g) {
    asm volatile("cp.async.ca.shared.global [%0], [%1], 16;" :: "r"(saddr), "l"(g));
}
__device__ __forceinline__ void mma_tf32(float* c, uint32_t a0, uint32_t a1, uint32_t a2, uint32_t a3,
                                         uint32_t b0, uint32_t b1) {
    asm volatile("mma.sync.aligned.m16n8k8.row.col.f32.tf32.tf32.f32 "
        "{%0,%1,%2,%3}, {%4,%5,%6,%7}, {%8,%9}, {%0,%1,%2,%3};"
        : "+f"(c[0]), "+f"(c[1]), "+f"(c[2]), "+f"(c[3])
        : "r"(a0), "r"(a1), "r"(a2), "r"(a3), "r"(b0), "r"(b1));
}

// ---------------- fold kernel ----------------
// Block k: col k of W_H=fuse_H@pwh, W_V=fuse_V@pwv, and dm1-folded rows; tf32-round into g_WA.
#define SMEM_FOLD ((128*129*2 + 32*129 + 4*128) * 4)
__global__ void __launch_bounds__(256) k_fold(
    const float* __restrict__ wf,   // [128][256]
    const float* __restrict__ pwh,  // [128][128]
    const float* __restrict__ pwv,  // [128][128]
    const float* __restrict__ dm1,  // [32][128]
    const float* __restrict__ dm2)  // [128][32]
{
    extern __shared__ float s[];
    float* FU = s;              // fuse_H [128][129]
    float* FV = s + 16512;      // fuse_V [128][129]
    float* D1 = s + 33024;      // dm1 [32][129]
    float* cH = s + 37152;      // [128] pw col, later dH
    float* cV = cH + 128;
    float* wH = cV + 128;       // [128]
    float* wV = wH + 128;
    const int k = blockIdx.x;
    const int tid = threadIdx.x;

    for (int i = tid; i < 128*128; i += 256) {
        int m = i >> 7, c = i & 127;
        FU[m*129 + c] = wf[m*256 + c];
        FV[m*129 + c] = wf[m*256 + 128 + c];
    }
    for (int i = tid; i < 32*128; i += 256)
        D1[(i >> 7)*129 + (i & 127)] = dm1[i];
    if (tid < 128) { cH[tid] = pwh[tid*128 + k]; cV[tid] = pwv[tid*128 + k]; }
    __syncthreads();

    {   // wH[m] = dot(fuse_H[m][:], pwh[:,k]); wV likewise
        int m = tid & 127;
        bool v = tid >= 128;
        const float* row = (v ? FV : FU) + m*129;
        const float* col = v ? cV : cH;
        float a = 0.f;
        #pragma unroll 8
        for (int c = 0; c < 128; ++c) a = fmaf(row[c], col[c], a);
        (v ? wV : wH)[m] = a;
    }
    __syncthreads();

    if (tid < 64) {  // dH[j] = dot(dm1[j][:], wH[:])
        int j = tid & 31;
        int t = tid >> 5;
        const float* w = t ? wV : wH;
        float a = 0.f;
        #pragma unroll 8
        for (int m = 0; m < 128; ++m) a = fmaf(D1[j*129 + m], w[m], a);
        (t ? cV : cH)[j] = a;
    }
    __syncthreads();

    for (int i = tid; i < 2*160; i += 256) {
        int t = i / 160, r = i - t*160;
        float val = (r < 128) ? (t ? wV : wH)[r] : (t ? cV : cH)[r - 128];
        g_WA[(size_t)(t*128 + k)*168 + r] = tf32r(val);
    }
    if (k == 0) {
        for (int i = tid; i < 128*32; i += 256) {
            int c = i >> 5, j = i & 31;
            g_dm2t[j*128 + c] = dm2[c*32 + j];
        }
    }
}

// ---------------- main fused kernel ----------------
// grid 2560 = 640 rows x 4 segments of 80; 320 threads; occ 2.
// smem floats: T[0,22528) [256][88]; Abuf[22528,25216) (2 x 8 x 168); dwhs[25216,25856); dwvs[25856,26496)
// overlays after GEMM: Esm [128][84] at 0 (10752 fl), Usm [32][88] at 10752 (2816 fl).
#define SMEM_MAIN (26496 * 4)
#define ACH_FL (8*168)          // floats per A chunk = 1344 (5376 B)

__global__ void __launch_bounds__(NTH, 2) k_main(
    const float* __restrict__ x,
    const float* __restrict__ dwh,      // [128][5]
    const float* __restrict__ dwv,      // [128][5]
    const float* __restrict__ scale_p,
    float* __restrict__ out)
{
    extern __shared__ float sm[];
    float* Tm   = sm;             // [256][88]
    float* abuf = sm + 22528;     // [2][8][168]
    float* dwhs = sm + 25216;
    float* dwvs = sm + 25856;
    float* Esm  = sm;             // overlay [c][p] stride 84
    float* Usm  = sm + 10752;     // overlay [j][p] stride 88

    const int tid  = threadIdx.x;
    const int lane = tid & 31;
    const int wrp  = tid >> 5;
    const int bx   = blockIdx.x;
    const int seg  = bx & 3;
    const int row  = bx >> 2;
    const int b    = row / HH;
    const int y    = row - b * HH;
    const int ai   = y % 5;
    const int y0   = y - ai;
    const int x0   = seg * SEG;

    const uint32_t abuf_s = (uint32_t)__cvta_generic_to_shared(abuf);

    // ---- prefetch A chunk 0 (overlaps stage 1) ----
    for (int i = tid; i < 336; i += NTH)
        cp_async16(abuf_s + i*16, (const char*)g_WA + i*16);
    asm volatile("cp.async.commit_group;");

    for (int i = tid; i < 640; i += NTH) { dwhs[i] = dwh[i]; dwvs[i] = dwv[i]; }
    __syncthreads();

    // ---- stage 1: depthwise convs + lrelu -> T rows (tf32-rounded) ----
    const float* xb = x + (size_t)b * C * HH * WW;
    #pragma unroll 2
    for (int it = 0; it < 32; ++it) {
        int i = tid + NTH * it;
        int k = i / SEG;
        int p = i - k * SEG;
        int aj = p % 5;
        const float* xp = xb + ((size_t)k * HH + y0) * WW + x0 + p;
        const float* xr = xb + ((size_t)k * HH + y)  * WW + x0 + p;
        float v0 = xp[0], v1 = xp[WW], v2 = xp[2*WW], v3 = xp[3*WW], v4 = xp[4*WW];
        float tv = 0.f;
        #pragma unroll
        for (int r = 0; r < 5; ++r) {
            int q = r - ai + 2;
            float vr = (r == 0) ? v0 : (r == 1) ? v1 : (r == 2) ? v2 : (r == 3) ? v3 : v4;
            if ((unsigned)q < 5u) tv = fmaf(dwvs[k*5 + q], vr, tv);
        }
        float vai = (ai == 0) ? v0 : (ai == 1) ? v1 : (ai == 2) ? v2 : (ai == 3) ? v3 : v4;
        float th = dwhs[k*5 + 2] * vai;
        if (aj >= 2) th = fmaf(dwhs[k*5 + 0], xr[-2], th);
        if (aj >= 1) th = fmaf(dwhs[k*5 + 1], xr[-1], th);
        if (aj <= 3) th = fmaf(dwhs[k*5 + 3], xr[ 1], th);
        if (aj <= 2) th = fmaf(dwhs[k*5 + 4], xr[ 2], th);
        Tm[k*88 + p]         = tf32r(lrelu(th));
        Tm[(128 + k)*88 + p] = tf32r(lrelu(tv));
    }

    // ---- GEMM via HMMA tf32: [160][80] = A @ T, m16n8k8 tiles ----
    // warp = 2 m-tiles (32 rows) x 5 n-tiles (40 px). mh = wrp%5, nh = wrp/5.
    const int mh  = wrp % 5;
    const int nh  = wrp / 5;
    const int gid = lane >> 2;     // 0..7
    const int tig = lane & 3;      // 0..3

    float acc[2][5][4];
    #pragma unroll
    for (int i = 0; i < 2; ++i)
        #pragma unroll
        for (int t = 0; t < 5; ++t)
            #pragma unroll
            for (int q = 0; q < 4; ++q) acc[i][t][q] = 0.f;

    for (int c = 0; c < 32; ++c) {
        __syncthreads();                       // buf (c+1)&1 free; also T ready at c==0
        if (c + 1 < 32) {
            uint32_t dst = abuf_s + ((c + 1) & 1) * (ACH_FL*4);
            const char* src = (const char*)g_WA + (size_t)(c + 1) * (ACH_FL*4);
            for (int i = tid; i < 336; i += NTH) cp_async16(dst + i*16, src + i*16);
        }
        asm volatile("cp.async.commit_group;");
        asm volatile("cp.async.wait_group 1;");
        __syncthreads();                       // chunk c visible

        const float* As  = abuf + (c & 1) * ACH_FL;
        const float* a0p = As + tig*168 + 32*mh + gid;        // col tig
        const float* a1p = As + (tig + 4)*168 + 32*mh + gid;  // col tig+4
        const float* b0p = Tm + (8*c + tig)*88 + 40*nh + gid;
        const float* b1p = b0p + 4*88;

        uint32_t a[2][4];
        #pragma unroll
        for (int i = 0; i < 2; ++i) {
            a[i][0] = __float_as_uint(a0p[16*i]);
            a[i][1] = __float_as_uint(a0p[16*i + 8]);
            a[i][2] = __float_as_uint(a1p[16*i]);
            a[i][3] = __float_as_uint(a1p[16*i + 8]);
        }
        #pragma unroll
        for (int t = 0; t < 5; ++t) {
            uint32_t b0 = __float_as_uint(b0p[8*t]);
            uint32_t b1 = __float_as_uint(b1p[8*t]);
            mma_tf32(acc[0][t], a[0][0], a[0][1], a[0][2], a[0][3], b0, b1);
            mma_tf32(acc[1][t], a[1][0], a[1][1], a[1][2], a[1][3], b0, b1);
        }
    }
    __syncthreads();   // done reading T before overlaying Esm/Usm

    // ---- scatter: epi rows -> Esm, dm1-folded rows (mh==4) -> lrelu -> Usm ----
    #pragma unroll
    for (int i = 0; i < 2; ++i) {
        int r = 32*mh + 16*i + gid;
        #pragma unroll
        for (int t = 0; t < 5; ++t) {
            int col = 40*nh + 8*t + 2*tig;
            if (mh < 4) {
                *(float2*)(Esm + r*84 + col)       = make_float2(acc[i][t][0], acc[i][t][1]);
                *(float2*)(Esm + (r + 8)*84 + col) = make_float2(acc[i][t][2], acc[i][t][3]);
            } else {
                int j = r - 128;
                *(float2*)(Usm + j*88 + col)       = make_float2(lrelu(acc[i][t][0]), lrelu(acc[i][t][1]));
                *(float2*)(Usm + (j + 8)*88 + col) = make_float2(lrelu(acc[i][t][2]), lrelu(acc[i][t][3]));
            }
        }
    }
    __syncthreads();

    // ---- dm2 @ u -> sigmoid gate; out = x + scl * epi * gate ----
    const int pq = tid % 10;      // 10 groups of 8 pixels
    const int cg = tid / 10;      // 32 groups of 4 channels
    const int c0 = cg * 4;
    const int q0 = pq * 8;
    u64 a2[4][4];
    #pragma unroll
    for (int i = 0; i < 4; ++i)
        #pragma unroll
        for (int s = 0; s < 4; ++s) a2[i][s] = 0ull;

    #pragma unroll 4
    for (int j = 0; j < 32; ++j) {
        float4 w = __ldg((const float4*)(g_dm2t + j*128 + c0));
        u64 w2[4] = { splat2(w.x), splat2(w.y), splat2(w.z), splat2(w.w) };
        ulonglong2 ua = *(const ulonglong2*)(Usm + j*88 + q0);
        ulonglong2 ub = *(const ulonglong2*)(Usm + j*88 + q0 + 4);
        u64 up[4] = { ua.x, ua.y, ub.x, ub.y };
        #pragma unroll
        for (int i = 0; i < 4; ++i)
            #pragma unroll
            for (int s = 0; s < 4; ++s) a2[i][s] = ffma2(w2[i], up[s], a2[i][s]);
    }

    const float scl = scale_p[0];
    #pragma unroll
    for (int i = 0; i < 4; ++i) {
        int c = c0 + i;
        size_t base = ((size_t)(b*C + c) * HH + y) * WW + x0 + q0;
        #pragma unroll
        for (int s = 0; s < 4; ++s) {
            float s0, s1;
            unpack2(a2[i][s], s0, s1);
            float d0 = __frcp_rn(1.f + __expf(-s0));
            float d1 = __frcp_rn(1.f + __expf(-s1));
            float e0, e1;
            unpack2(*(const u64*)(Esm + c*84 + q0 + 2*s), e0, e1);
            float2 xv = *(const float2*)(x + base + 2*s);
            float2 o;
            o.x = fmaf(scl * d0, e0, xv.x);
            o.y = fmaf(scl * d1, e1, xv.y);
            *(float2*)(out + base + 2*s) = o;
        }
    }
}

// ---------------- launch ----------------
extern "C" void kernel_launch(void* const* d_in, const int* in_sizes, int n_in,
                              void* d_out, int out_size) {
    (void)in_sizes; (void)n_in; (void)out_size;
    const float* x      = (const float*)d_in[0];
    const float* w_h_dw = (const float*)d_in[1];
    const float* w_h_pw = (const float*)d_in[2];
    const float* w_v_dw = (const float*)d_in[3];
    const float* w_v_pw = (const float*)d_in[4];
    const float* w_dm1  = (const float*)d_in[5];
    const float* w_dm2  = (const float*)d_in[6];
    const float* w_fuse = (const float*)d_in[7];
    const float* scale  = (const float*)d_in[8];
    float* out = (float*)d_out;

    cudaFuncSetAttribute(k_fold, cudaFuncAttributeMaxDynamicSharedMemorySize, SMEM_FOLD);
    cudaFuncSetAttribute(k_main, cudaFuncAttributeMaxDynamicSharedMemorySize, SMEM_MAIN);

    k_fold<<<128, 256, SMEM_FOLD>>>(w_fuse, w_h_pw, w_v_pw, w_dm1, w_dm2);
    k_main<<<NBLK, NTH, SMEM_MAIN>>>(x, w_h_dw, w_v_dw, scale, out);
}